// round 13
// baseline (speedup 1.0000x reference)
#include <cuda_runtime.h>
#include <mma.h>
#include <math.h>
#include <cstdint>

using namespace nvcuda;

#define HID 128
#define MAXN_PAD 50048
#define MAXE 800000
#define SM1_BLOCKS 512
#define LDA 132
#define TFL (128 * LDA)

// k_tedge smem (floats): b1s[128], w2s[128], Bs[TFL], A0[TFL], A1[TFL]
#define SMEM_EDGE ((256 + 3 * TFL) * 4)
// k_tguv smem (floats): pad[256], As[TFL], Bs[TFL]
#define SMEM_UV ((256 + 2 * TFL) * 4)

__device__ float g_u[MAXN_PAD * HID];
__device__ float g_v[MAXN_PAD * HID];
__device__ float g_a[MAXE];
__device__ float g_pm[SM1_BLOCKS];
__device__ float g_ps[SM1_BLOCKS];
__device__ float g_M, g_S;

// ---------------------------------------------------------------------------
__device__ __forceinline__ uint32_t smem_u32(const void* p) {
    uint32_t a;
    asm("{ .reg .u64 t; cvta.to.shared.u64 t, %1; cvt.u32.u64 %0, t; }"
        : "=r"(a) : "l"(p));
    return a;
}

// async-copy one 128x128 A tile (row-major, LDA pad), zero-fill OOB rows
__device__ __forceinline__ void issue_A(const float* __restrict__ src, int m_base,
                                        int n_rows, float* dst, int tid) {
    #pragma unroll
    for (int i = tid; i < 128 * 32; i += 256) {
        int r = i >> 5, q = i & 31;
        int m = m_base + r;
        float* d = dst + r * LDA + q * 4;
        if (m < n_rows) {
            uint32_t da = smem_u32(d);
            asm volatile("cp.async.cg.shared.global [%0], [%1], 16;"
                         :: "r"(da), "l"(src + (size_t)m * HID + q * 4) : "memory");
        } else {
            *reinterpret_cast<float4*>(d) = make_float4(0.f, 0.f, 0.f, 0.f);
        }
    }
    asm volatile("cp.async.commit_group;" ::: "memory");
}

__device__ __forceinline__ void load_B_sync(const float* __restrict__ W,
                                            float* Bs, int tid) {
    #pragma unroll
    for (int i = tid; i < 128 * 32; i += 256) {
        int k = i >> 5, q = i & 31;
        *reinterpret_cast<float4*>(Bs + k * LDA + q * 4) =
            reinterpret_cast<const float4*>(W + (size_t)k * HID)[q];
    }
}

using AccFrag = wmma::fragment<wmma::accumulator, 16, 16, 8, float>;

__device__ __forceinline__ void mma_loop(const float* As, const float* Bs,
                                         int wm, int wn, AccFrag acc[4][2]) {
    #pragma unroll
    for (int i = 0; i < 4; ++i)
        #pragma unroll
        for (int j = 0; j < 2; ++j)
            wmma::fill_fragment(acc[i][j], 0.f);

    #pragma unroll 4
    for (int kk = 0; kk < 128; kk += 8) {
        wmma::fragment<wmma::matrix_a, 16, 16, 8, wmma::precision::tf32,
                       wmma::row_major> af[4];
        wmma::fragment<wmma::matrix_b, 16, 16, 8, wmma::precision::tf32,
                       wmma::row_major> bf[2];
        #pragma unroll
        for (int i = 0; i < 4; ++i) {
            wmma::load_matrix_sync(af[i], As + (wm + i * 16) * LDA + kk, LDA);
            #pragma unroll
            for (int t = 0; t < af[i].num_elements; ++t)
                af[i].x[t] = wmma::__float_to_tf32(af[i].x[t]);
        }
        #pragma unroll
        for (int j = 0; j < 2; ++j) {
            wmma::load_matrix_sync(bf[j], Bs + kk * LDA + wn + j * 16, LDA);
            #pragma unroll
            for (int t = 0; t < bf[j].num_elements; ++t)
                bf[j].x[t] = wmma::__float_to_tf32(bf[j].x[t]);
        }
        #pragma unroll
        for (int i = 0; i < 4; ++i)
            #pragma unroll
            for (int j = 0; j < 2; ++j)
                wmma::mma_sync(acc[i][j], af[i], bf[j], acc[i][j]);
    }
}

// ---------------------------------------------------------------------------
// K1: u = h@Wa and v = h@Wb in one kernel (A tile loaded once)
// ---------------------------------------------------------------------------
__global__ void __launch_bounds__(256, 1)
k_tguv(const float* __restrict__ A, const float* __restrict__ W1, int n_rows) {
    extern __shared__ float smf[];
    float* As = smf + 256;
    float* Bs = smf + 256 + TFL;
    int tid = threadIdx.x, wid = tid >> 5;
    int m_base = blockIdx.x * 128;
    int wm = (wid >> 2) * 64, wn = (wid & 3) * 32;

    issue_A(A, m_base, n_rows, As, tid);
    load_B_sync(W1, Bs, tid);
    asm volatile("cp.async.wait_group 0;" ::: "memory");
    __syncthreads();

    AccFrag acc[4][2];
    mma_loop(As, Bs, wm, wn, acc);
    #pragma unroll
    for (int i = 0; i < 4; ++i)
        #pragma unroll
        for (int j = 0; j < 2; ++j)
            wmma::store_matrix_sync(
                g_u + (size_t)(m_base + wm + i * 16) * HID + wn + j * 16,
                acc[i][j], HID, wmma::mem_row_major);
    __syncthreads();

    load_B_sync(W1 + HID * HID, Bs, tid);
    __syncthreads();
    mma_loop(As, Bs, wm, wn, acc);
    #pragma unroll
    for (int i = 0; i < 4; ++i)
        #pragma unroll
        for (int j = 0; j < 2; ++j)
            wmma::store_matrix_sync(
                g_v + (size_t)(m_base + wm + i * 16) * HID + wn + j * 16,
                acc[i][j], HID, wmma::mem_row_major);
}

// ---------------------------------------------------------------------------
// K2: persistent edge kernel — B resident, double-buffered A, fused epilogue
// ---------------------------------------------------------------------------
__global__ void __launch_bounds__(256, 1)
k_tedge(const float* __restrict__ ea, const float* __restrict__ Wc,
        const int* __restrict__ ei,
        const float* __restrict__ b1, const float* __restrict__ W2,
        const float* __restrict__ b2, int n_edges) {
    extern __shared__ float smf[];
    float* b1s = smf;
    float* w2s = smf + 128;
    float* Bs  = smf + 256;
    float* Ab0 = smf + 256 + TFL;
    float* Ab1 = smf + 256 + 2 * TFL;

    int tid = threadIdx.x, wid = tid >> 5;
    int wm = (wid >> 2) * 64, wn = (wid & 3) * 32;

    if (tid < 128) { b1s[tid] = b1[tid]; w2s[tid] = W2[tid]; }
    load_B_sync(Wc, Bs, tid);
    float bias2 = b2[0];

    int nt = (n_edges + 127) >> 7;
    int t = blockIdx.x;
    if (t < nt) issue_A(ea, t << 7, n_edges, Ab0, tid);

    int it = 0;
    for (; t < nt; t += gridDim.x, ++it) {
        float* Acur = (it & 1) ? Ab1 : Ab0;
        float* Anxt = (it & 1) ? Ab0 : Ab1;
        int tn = t + gridDim.x;
        if (tn < nt) {
            issue_A(ea, tn << 7, n_edges, Anxt, tid);
            asm volatile("cp.async.wait_group 1;" ::: "memory");
        } else {
            asm volatile("cp.async.wait_group 0;" ::: "memory");
        }
        __syncthreads();

        AccFrag acc[4][2];
        mma_loop(Acur, Bs, wm, wn, acc);
        __syncthreads();
        #pragma unroll
        for (int i = 0; i < 4; ++i)
            #pragma unroll
            for (int j = 0; j < 2; ++j)
                wmma::store_matrix_sync(Acur + (wm + i * 16) * LDA + wn + j * 16,
                                        acc[i][j], LDA, wmma::mem_row_major);
        __syncthreads();

        // Epilogue: 2 threads per edge row; each owns 64 cols
        int er = tid >> 1;
        int e = (t << 7) + er;
        float s = 0.f;
        if (e < n_edges) {
            int r = ei[e];
            int c = ei[n_edges + e];
            int qo = (tid & 1) * 16;
            const float4* cp4 = reinterpret_cast<const float4*>(Acur + er * LDA) + qo;
            const float4* up  = reinterpret_cast<const float4*>(g_u + (size_t)r * HID) + qo;
            const float4* vp  = reinterpret_cast<const float4*>(g_v + (size_t)c * HID) + qo;
            const float4* bb4 = reinterpret_cast<const float4*>(b1s) + qo;
            const float4* ww4 = reinterpret_cast<const float4*>(w2s) + qo;
            #pragma unroll 4
            for (int q = 0; q < 16; ++q) {
                float4 cv = cp4[q], uu = up[q], vv = vp[q], bb = bb4[q], ww = ww4[q];
                float p0 = cv.x + uu.x + vv.x + bb.x;
                float p1 = cv.y + uu.y + vv.y + bb.y;
                float p2 = cv.z + uu.z + vv.z + bb.z;
                float p3 = cv.w + uu.w + vv.w + bb.w;
                float e0 = p0 > 0.f ? p0 : expm1f(p0);
                float e1 = p1 > 0.f ? p1 : expm1f(p1);
                float e2 = p2 > 0.f ? p2 : expm1f(p2);
                float e3 = p3 > 0.f ? p3 : expm1f(p3);
                s = fmaf(e0, ww.x, s);
                s = fmaf(e1, ww.y, s);
                s = fmaf(e2, ww.z, s);
                s = fmaf(e3, ww.w, s);
            }
        }
        s += __shfl_xor_sync(0xffffffffu, s, 1);
        if ((tid & 1) == 0 && e < n_edges) {
            float av = s + bias2;
            av = av >= 0.f ? av : 0.2f * av;
            g_a[e] = av;
        }
        __syncthreads();
    }
}

// ---------------------------------------------------------------------------
// K3/K4: global softmax reduction
// ---------------------------------------------------------------------------
__global__ void k_sm1(int n) {
    __shared__ float sh[256];
    int tid = threadIdx.x;
    float m = -1e30f;
    for (int i = blockIdx.x * 256 + tid; i < n; i += gridDim.x * 256)
        m = fmaxf(m, g_a[i]);
    sh[tid] = m; __syncthreads();
    for (int off = 128; off > 0; off >>= 1) {
        if (tid < off) sh[tid] = fmaxf(sh[tid], sh[tid + off]);
        __syncthreads();
    }
    float bm = sh[0]; __syncthreads();
    float s = 0.f;
    for (int i = blockIdx.x * 256 + tid; i < n; i += gridDim.x * 256)
        s += expf(g_a[i] - bm);
    sh[tid] = s; __syncthreads();
    for (int off = 128; off > 0; off >>= 1) {
        if (tid < off) sh[tid] += sh[tid + off];
        __syncthreads();
    }
    if (tid == 0) { g_pm[blockIdx.x] = bm; g_ps[blockIdx.x] = sh[0]; }
}

__global__ void k_sm2() {
    __shared__ float sh[SM1_BLOCKS];
    int tid = threadIdx.x;
    sh[tid] = g_pm[tid]; __syncthreads();
    for (int off = SM1_BLOCKS / 2; off > 0; off >>= 1) {
        if (tid < off) sh[tid] = fmaxf(sh[tid], sh[tid + off]);
        __syncthreads();
    }
    float M = sh[0]; __syncthreads();
    sh[tid] = g_ps[tid] * expf(g_pm[tid] - M); __syncthreads();
    for (int off = SM1_BLOCKS / 2; off > 0; off >>= 1) {
        if (tid < off) sh[tid] += sh[tid + off];
        __syncthreads();
    }
    if (tid == 0) { g_M = M; g_S = sh[0]; }
}

// ---------------------------------------------------------------------------
// K5/K6: zero + scatter (vector red.global.add.v4.f32)
// ---------------------------------------------------------------------------
__global__ void k_zero(float* __restrict__ out, int n) {
    for (int i = blockIdx.x * blockDim.x + threadIdx.x; i < n;
         i += gridDim.x * blockDim.x)
        out[i] = 0.f;
}

__global__ void k_scatter(const int* __restrict__ ei,
                          const float* __restrict__ h,
                          float* __restrict__ out, int n_edges) {
    int gw = (blockIdx.x * blockDim.x + threadIdx.x) >> 5;
    int lane = threadIdx.x & 31;
    int nw = (gridDim.x * blockDim.x) >> 5;
    float M = g_M;
    float invS = 1.0f / g_S;
    for (int e = gw; e < n_edges; e += nw) {
        int r = ei[e];
        int c = ei[n_edges + e];
        float alpha = expf(g_a[e] - M) * invS;
        float4 hv = reinterpret_cast<const float4*>(h + (size_t)c * HID)[lane];
        float* op = out + (size_t)r * HID + lane * 4;
        asm volatile("red.global.add.v4.f32 [%0], {%1, %2, %3, %4};"
                     :: "l"(op), "f"(alpha * hv.x), "f"(alpha * hv.y),
                        "f"(alpha * hv.z), "f"(alpha * hv.w) : "memory");
    }
}

// ---------------------------------------------------------------------------
extern "C" void kernel_launch(void* const* d_in, const int* in_sizes, int n_in,
                              void* d_out, int out_size) {
    const float* h  = (const float*)d_in[0];
    const int*   ei = (const int*)d_in[1];
    const float* ea = (const float*)d_in[2];
    const float* W1 = (const float*)d_in[3];
    const float* b1 = (const float*)d_in[4];
    const float* W2 = (const float*)d_in[5];
    const float* b2 = (const float*)d_in[6];
    float* out = (float*)d_out;

    int n_nodes = in_sizes[0] / HID;
    int n_edges = in_sizes[2] / HID;

    cudaFuncSetAttribute(k_tguv,  cudaFuncAttributeMaxDynamicSharedMemorySize, SMEM_UV);
    cudaFuncSetAttribute(k_tedge, cudaFuncAttributeMaxDynamicSharedMemorySize, SMEM_EDGE);

    int node_blocks = (n_nodes + 127) / 128;

    k_zero<<<2048, 256>>>(out, n_nodes * HID);
    k_tguv<<<node_blocks, 256, SMEM_UV>>>(h, W1, n_nodes);
    k_tedge<<<148, 256, SMEM_EDGE>>>(ea, W1 + 2 * HID * HID, ei, b1, W2, b2, n_edges);
    k_sm1<<<SM1_BLOCKS, 256>>>(n_edges);
    k_sm2<<<1, SM1_BLOCKS>>>();
    k_scatter<<<4096, 256>>>(ei, h, out, n_edges);
}

// round 14
// speedup vs baseline: 1.3863x; 1.3863x over previous
#include <cuda_runtime.h>
#include <mma.h>
#include <math.h>
#include <cstdint>

using namespace nvcuda;

#define HID 128
#define MAXN_PAD 50048
#define MAXE 800000
#define SM1_BLOCKS 512
#define LDA 132
#define A_FL (64 * LDA)
#define B_FL (128 * LDA)

// smem (floats): b1s[128], w2s[128], As[64*LDA], Bs[128*LDA]  => 100.0 KB
#define SMF_A 256
#define SMF_B (256 + A_FL)
#define SMEM_TILE ((256 + A_FL + B_FL) * 4)

__device__ float g_u[MAXN_PAD * HID];
__device__ float g_v[MAXN_PAD * HID];
__device__ float g_a[MAXE];
__device__ float g_pm[SM1_BLOCKS];
__device__ float g_ps[SM1_BLOCKS];
__device__ float g_M, g_S;

// ---------------------------------------------------------------------------
__device__ __forceinline__ uint32_t smem_u32(const void* p) {
    uint32_t a;
    asm("{ .reg .u64 t; cvta.to.shared.u64 t, %1; cvt.u32.u64 %0, t; }"
        : "=r"(a) : "l"(p));
    return a;
}

// async-copy one 64x128 A tile (row-major, LDA pad), zero-fill OOB rows
__device__ __forceinline__ void issue_A64(const float* __restrict__ src, int m_base,
                                          int n_rows, float* dst, int tid) {
    #pragma unroll
    for (int i = tid; i < 64 * 32; i += 256) {
        int r = i >> 5, q = i & 31;
        int m = m_base + r;
        float* d = dst + r * LDA + q * 4;
        if (m < n_rows) {
            asm volatile("cp.async.cg.shared.global [%0], [%1], 16;"
                         :: "r"(smem_u32(d)), "l"(src + (size_t)m * HID + q * 4)
                         : "memory");
        } else {
            *reinterpret_cast<float4*>(d) = make_float4(0.f, 0.f, 0.f, 0.f);
        }
    }
    asm volatile("cp.async.commit_group;" ::: "memory");
}

__device__ __forceinline__ void load_B_sync(const float* __restrict__ W,
                                            float* Bs, int tid) {
    #pragma unroll
    for (int i = tid; i < 128 * 32; i += 256) {
        int k = i >> 5, q = i & 31;
        *reinterpret_cast<float4*>(Bs + k * LDA + q * 4) =
            reinterpret_cast<const float4*>(W + (size_t)k * HID)[q];
    }
}

using AccFrag = wmma::fragment<wmma::accumulator, 16, 16, 8, float>;

// warp (wm, wn) computes 32x32 of C = A[64x128] @ B[128x128]
__device__ __forceinline__ void mma_loop64(const float* As, const float* Bs,
                                           int wm, int wn, AccFrag acc[2][2]) {
    #pragma unroll
    for (int i = 0; i < 2; ++i)
        #pragma unroll
        for (int j = 0; j < 2; ++j)
            wmma::fill_fragment(acc[i][j], 0.f);

    #pragma unroll 4
    for (int kk = 0; kk < 128; kk += 8) {
        wmma::fragment<wmma::matrix_a, 16, 16, 8, wmma::precision::tf32,
                       wmma::row_major> af[2];
        wmma::fragment<wmma::matrix_b, 16, 16, 8, wmma::precision::tf32,
                       wmma::row_major> bf[2];
        #pragma unroll
        for (int i = 0; i < 2; ++i) {
            wmma::load_matrix_sync(af[i], As + (wm + i * 16) * LDA + kk, LDA);
            #pragma unroll
            for (int t = 0; t < af[i].num_elements; ++t)
                af[i].x[t] = wmma::__float_to_tf32(af[i].x[t]);
        }
        #pragma unroll
        for (int j = 0; j < 2; ++j) {
            wmma::load_matrix_sync(bf[j], Bs + kk * LDA + wn + j * 16, LDA);
            #pragma unroll
            for (int t = 0; t < bf[j].num_elements; ++t)
                bf[j].x[t] = wmma::__float_to_tf32(bf[j].x[t]);
        }
        #pragma unroll
        for (int i = 0; i < 2; ++i)
            #pragma unroll
            for (int j = 0; j < 2; ++j)
                wmma::mma_sync(acc[i][j], af[i], bf[j], acc[i][j]);
    }
}

// ---------------------------------------------------------------------------
// K1: u = h@Wa and v = h@Wb (64-row tiles, A loaded once, 2 CTAs/SM)
// ---------------------------------------------------------------------------
__global__ void __launch_bounds__(256, 2)
k_tguv(const float* __restrict__ A, const float* __restrict__ W1, int n_rows) {
    extern __shared__ float smf[];
    float* As = smf + SMF_A;
    float* Bs = smf + SMF_B;
    int tid = threadIdx.x, wid = tid >> 5;
    int m_base = blockIdx.x * 64;
    int wm = (wid >> 2) * 32, wn = (wid & 3) * 32;

    issue_A64(A, m_base, n_rows, As, tid);
    load_B_sync(W1, Bs, tid);
    asm volatile("cp.async.wait_group 0;" ::: "memory");
    __syncthreads();

    AccFrag acc[2][2];
    mma_loop64(As, Bs, wm, wn, acc);
    #pragma unroll
    for (int i = 0; i < 2; ++i)
        #pragma unroll
        for (int j = 0; j < 2; ++j)
            wmma::store_matrix_sync(
                g_u + (size_t)(m_base + wm + i * 16) * HID + wn + j * 16,
                acc[i][j], HID, wmma::mem_row_major);
    __syncthreads();

    load_B_sync(W1 + HID * HID, Bs, tid);
    __syncthreads();
    mma_loop64(As, Bs, wm, wn, acc);
    #pragma unroll
    for (int i = 0; i < 2; ++i)
        #pragma unroll
        for (int j = 0; j < 2; ++j)
            wmma::store_matrix_sync(
                g_v + (size_t)(m_base + wm + i * 16) * HID + wn + j * 16,
                acc[i][j], HID, wmma::mem_row_major);
}

// ---------------------------------------------------------------------------
// K2: edge GEMM (64 edges/block) + fused logit epilogue, 2 CTAs/SM
// ---------------------------------------------------------------------------
__global__ void __launch_bounds__(256, 2)
k_tedge(const float* __restrict__ ea, const float* __restrict__ Wc,
        const int* __restrict__ ei,
        const float* __restrict__ b1, const float* __restrict__ W2,
        const float* __restrict__ b2, int n_edges) {
    extern __shared__ float smf[];
    float* b1s = smf;
    float* w2s = smf + 128;
    float* As  = smf + SMF_A;
    float* Bs  = smf + SMF_B;
    int tid = threadIdx.x, wid = tid >> 5;
    int m_base = blockIdx.x * 64;
    int wm = (wid >> 2) * 32, wn = (wid & 3) * 32;

    if (tid < 128) { b1s[tid] = b1[tid]; w2s[tid] = W2[tid]; }
    issue_A64(ea, m_base, n_edges, As, tid);
    load_B_sync(Wc, Bs, tid);
    asm volatile("cp.async.wait_group 0;" ::: "memory");
    __syncthreads();

    AccFrag acc[2][2];
    mma_loop64(As, Bs, wm, wn, acc);
    __syncthreads();                 // all reads of As done before reuse as Cs

    float* Cs = As;
    #pragma unroll
    for (int i = 0; i < 2; ++i)
        #pragma unroll
        for (int j = 0; j < 2; ++j)
            wmma::store_matrix_sync(Cs + (wm + i * 16) * LDA + wn + j * 16,
                                    acc[i][j], LDA, wmma::mem_row_major);
    __syncthreads();

    // Epilogue: 4 threads per edge row, each owns 32 cols (8 float4)
    int er = tid >> 2;               // 0..63
    int part = tid & 3;
    int e = m_base + er;
    float s = 0.f;
    if (e < n_edges) {
        int r = ei[e];
        int c = ei[n_edges + e];
        int qo = part * 8;
        const float4* cp4 = reinterpret_cast<const float4*>(Cs + er * LDA) + qo;
        const float4* up  = reinterpret_cast<const float4*>(g_u + (size_t)r * HID) + qo;
        const float4* vp  = reinterpret_cast<const float4*>(g_v + (size_t)c * HID) + qo;
        const float4* bb4 = reinterpret_cast<const float4*>(b1s) + qo;
        const float4* ww4 = reinterpret_cast<const float4*>(w2s) + qo;
        #pragma unroll
        for (int q = 0; q < 8; ++q) {
            float4 cv = cp4[q], uu = up[q], vv = vp[q], bb = bb4[q], ww = ww4[q];
            float p0 = cv.x + uu.x + vv.x + bb.x;
            float p1 = cv.y + uu.y + vv.y + bb.y;
            float p2 = cv.z + uu.z + vv.z + bb.z;
            float p3 = cv.w + uu.w + vv.w + bb.w;
            float e0 = p0 > 0.f ? p0 : expm1f(p0);
            float e1 = p1 > 0.f ? p1 : expm1f(p1);
            float e2 = p2 > 0.f ? p2 : expm1f(p2);
            float e3 = p3 > 0.f ? p3 : expm1f(p3);
            s = fmaf(e0, ww.x, s);
            s = fmaf(e1, ww.y, s);
            s = fmaf(e2, ww.z, s);
            s = fmaf(e3, ww.w, s);
        }
    }
    s += __shfl_xor_sync(0xffffffffu, s, 1);
    s += __shfl_xor_sync(0xffffffffu, s, 2);
    if (part == 0 && e < n_edges) {
        float av = s + b2[0];
        av = av >= 0.f ? av : 0.2f * av;
        g_a[e] = av;
    }
}

// ---------------------------------------------------------------------------
// K3/K4: global softmax reduction
// ---------------------------------------------------------------------------
__global__ void k_sm1(int n) {
    __shared__ float sh[256];
    int tid = threadIdx.x;
    float m = -1e30f;
    for (int i = blockIdx.x * 256 + tid; i < n; i += gridDim.x * 256)
        m = fmaxf(m, g_a[i]);
    sh[tid] = m; __syncthreads();
    for (int off = 128; off > 0; off >>= 1) {
        if (tid < off) sh[tid] = fmaxf(sh[tid], sh[tid + off]);
        __syncthreads();
    }
    float bm = sh[0]; __syncthreads();
    float s = 0.f;
    for (int i = blockIdx.x * 256 + tid; i < n; i += gridDim.x * 256)
        s += expf(g_a[i] - bm);
    sh[tid] = s; __syncthreads();
    for (int off = 128; off > 0; off >>= 1) {
        if (tid < off) sh[tid] += sh[tid + off];
        __syncthreads();
    }
    if (tid == 0) { g_pm[blockIdx.x] = bm; g_ps[blockIdx.x] = sh[0]; }
}

__global__ void k_sm2() {
    __shared__ float sh[SM1_BLOCKS];
    int tid = threadIdx.x;
    sh[tid] = g_pm[tid]; __syncthreads();
    for (int off = SM1_BLOCKS / 2; off > 0; off >>= 1) {
        if (tid < off) sh[tid] = fmaxf(sh[tid], sh[tid + off]);
        __syncthreads();
    }
    float M = sh[0]; __syncthreads();
    sh[tid] = g_ps[tid] * expf(g_pm[tid] - M); __syncthreads();
    for (int off = SM1_BLOCKS / 2; off > 0; off >>= 1) {
        if (tid < off) sh[tid] += sh[tid + off];
        __syncthreads();
    }
    if (tid == 0) { g_M = M; g_S = sh[0]; }
}

// ---------------------------------------------------------------------------
// K5/K6: zero + scatter (vector red.global.add.v4.f32)
// ---------------------------------------------------------------------------
__global__ void k_zero(float* __restrict__ out, int n) {
    for (int i = blockIdx.x * blockDim.x + threadIdx.x; i < n;
         i += gridDim.x * blockDim.x)
        out[i] = 0.f;
}

__global__ void k_scatter(const int* __restrict__ ei,
                          const float* __restrict__ h,
                          float* __restrict__ out, int n_edges) {
    int gw = (blockIdx.x * blockDim.x + threadIdx.x) >> 5;
    int lane = threadIdx.x & 31;
    int nw = (gridDim.x * blockDim.x) >> 5;
    float M = g_M;
    float invS = 1.0f / g_S;
    for (int e = gw; e < n_edges; e += nw) {
        int r = ei[e];
        int c = ei[n_edges + e];
        float alpha = expf(g_a[e] - M) * invS;
        float4 hv = reinterpret_cast<const float4*>(h + (size_t)c * HID)[lane];
        float* op = out + (size_t)r * HID + lane * 4;
        asm volatile("red.global.add.v4.f32 [%0], {%1, %2, %3, %4};"
                     :: "l"(op), "f"(alpha * hv.x), "f"(alpha * hv.y),
                        "f"(alpha * hv.z), "f"(alpha * hv.w) : "memory");
    }
}

// ---------------------------------------------------------------------------
extern "C" void kernel_launch(void* const* d_in, const int* in_sizes, int n_in,
                              void* d_out, int out_size) {
    const float* h  = (const float*)d_in[0];
    const int*   ei = (const int*)d_in[1];
    const float* ea = (const float*)d_in[2];
    const float* W1 = (const float*)d_in[3];
    const float* b1 = (const float*)d_in[4];
    const float* W2 = (const float*)d_in[5];
    const float* b2 = (const float*)d_in[6];
    float* out = (float*)d_out;

    int n_nodes = in_sizes[0] / HID;
    int n_edges = in_sizes[2] / HID;

    cudaFuncSetAttribute(k_tguv,  cudaFuncAttributeMaxDynamicSharedMemorySize, SMEM_TILE);
    cudaFuncSetAttribute(k_tedge, cudaFuncAttributeMaxDynamicSharedMemorySize, SMEM_TILE);

    int node_blocks = (n_nodes + 63) / 64;
    int edge_blocks = (n_edges + 63) / 64;

    k_zero<<<2048, 256>>>(out, n_nodes * HID);
    k_tguv<<<node_blocks, 256, SMEM_TILE>>>(h, W1, n_nodes);
    k_tedge<<<edge_blocks, 256, SMEM_TILE>>>(ea, W1 + 2 * HID * HID, ei, b1, W2, b2, n_edges);
    k_sm1<<<SM1_BLOCKS, 256>>>(n_edges);
    k_sm2<<<1, SM1_BLOCKS>>>();
    k_scatter<<<4096, 256>>>(ei, h, out, n_edges);
}

// round 15
// speedup vs baseline: 2.4885x; 1.7951x over previous
#include <cuda_runtime.h>
#include <mma.h>
#include <cuda_fp16.h>
#include <math.h>
#include <cstdint>

using namespace nvcuda;

#define HID 128
#define MAXN_PAD 50048
#define MAXE 800000
#define SM1_BLOCKS 512
#define LDAH 136            // half-elem pitch (272B rows, conflict-free-ish)
#define LDC  132            // float pitch for C tile

// smem bytes: b1s/w2s 1024 | Ah 64*136*2=17408 | Bh 128*136*2=34816 (C reuses Bh)
#define OFF_AH 1024
#define OFF_BH (1024 + 17408)
#define SMEM_TILE (1024 + 17408 + 34816)

__device__ float g_u[MAXN_PAD * HID];
__device__ float g_v[MAXN_PAD * HID];
__device__ float g_a[MAXE];
__device__ float g_pm[SM1_BLOCKS];
__device__ float g_ps[SM1_BLOCKS];
__device__ float g_M, g_S;

// ---------------------------------------------------------------------------
// Loaders: global fp32 -> smem fp16 (rounded), zero-filled OOB rows
// ---------------------------------------------------------------------------
__device__ __forceinline__ void load_A16(const float* __restrict__ src, int m_base,
                                         int n_rows, __half* Ah, int tid) {
    #pragma unroll
    for (int i = tid; i < 64 * 32; i += 256) {
        int r = i >> 5, q = i & 31;
        int m = m_base + r;
        __half2 h0 = __floats2half2_rn(0.f, 0.f), h1 = h0;
        if (m < n_rows) {
            float4 v = reinterpret_cast<const float4*>(src + (size_t)m * HID)[q];
            h0 = __floats2half2_rn(v.x, v.y);
            h1 = __floats2half2_rn(v.z, v.w);
        }
        __half2* d = reinterpret_cast<__half2*>(Ah + r * LDAH + q * 4);
        d[0] = h0; d[1] = h1;
    }
}

__device__ __forceinline__ void load_B16(const float* __restrict__ W,
                                         __half* Bh, int tid) {
    #pragma unroll
    for (int i = tid; i < 128 * 32; i += 256) {
        int k = i >> 5, q = i & 31;
        float4 v = reinterpret_cast<const float4*>(W + (size_t)k * HID)[q];
        __half2* d = reinterpret_cast<__half2*>(Bh + k * LDAH + q * 4);
        d[0] = __floats2half2_rn(v.x, v.y);
        d[1] = __floats2half2_rn(v.z, v.w);
    }
}

using AFrag = wmma::fragment<wmma::matrix_a, 16, 16, 16, __half, wmma::row_major>;
using BFrag = wmma::fragment<wmma::matrix_b, 16, 16, 16, __half, wmma::row_major>;
using CFrag = wmma::fragment<wmma::accumulator, 16, 16, 16, float>;

// warp (wm, wn) computes 32x32 of C = A[64x128] @ B[128x128], fp16 in fp32 acc
__device__ __forceinline__ void mma_loop16(const __half* Ah, const __half* Bh,
                                           int wm, int wn, CFrag acc[2][2]) {
    #pragma unroll
    for (int i = 0; i < 2; ++i)
        #pragma unroll
        for (int j = 0; j < 2; ++j)
            wmma::fill_fragment(acc[i][j], 0.f);

    #pragma unroll
    for (int kk = 0; kk < 128; kk += 16) {
        AFrag af[2];
        BFrag bf[2];
        #pragma unroll
        for (int i = 0; i < 2; ++i)
            wmma::load_matrix_sync(af[i], Ah + (wm + i * 16) * LDAH + kk, LDAH);
        #pragma unroll
        for (int j = 0; j < 2; ++j)
            wmma::load_matrix_sync(bf[j], Bh + kk * LDAH + wn + j * 16, LDAH);
        #pragma unroll
        for (int i = 0; i < 2; ++i)
            #pragma unroll
            for (int j = 0; j < 2; ++j)
                wmma::mma_sync(acc[i][j], af[i], bf[j], acc[i][j]);
    }
}

// ---------------------------------------------------------------------------
// K1: u = h@Wa and v = h@Wb (64-row tiles, A converted once, 3 CTAs/SM)
// ---------------------------------------------------------------------------
__global__ void __launch_bounds__(256, 3)
k_tguv(const float* __restrict__ A, const float* __restrict__ W1, int n_rows) {
    extern __shared__ char smraw[];
    __half* Ah = reinterpret_cast<__half*>(smraw + OFF_AH);
    __half* Bh = reinterpret_cast<__half*>(smraw + OFF_BH);
    int tid = threadIdx.x, wid = tid >> 5;
    int m_base = blockIdx.x * 64;
    int wm = (wid >> 2) * 32, wn = (wid & 3) * 32;

    load_A16(A, m_base, n_rows, Ah, tid);
    load_B16(W1, Bh, tid);
    __syncthreads();

    CFrag acc[2][2];
    mma_loop16(Ah, Bh, wm, wn, acc);
    #pragma unroll
    for (int i = 0; i < 2; ++i)
        #pragma unroll
        for (int j = 0; j < 2; ++j)
            wmma::store_matrix_sync(
                g_u + (size_t)(m_base + wm + i * 16) * HID + wn + j * 16,
                acc[i][j], HID, wmma::mem_row_major);
    __syncthreads();

    load_B16(W1 + HID * HID, Bh, tid);
    __syncthreads();
    mma_loop16(Ah, Bh, wm, wn, acc);
    #pragma unroll
    for (int i = 0; i < 2; ++i)
        #pragma unroll
        for (int j = 0; j < 2; ++j)
            wmma::store_matrix_sync(
                g_v + (size_t)(m_base + wm + i * 16) * HID + wn + j * 16,
                acc[i][j], HID, wmma::mem_row_major);
}

// ---------------------------------------------------------------------------
// K2: edge GEMM (64 edges/block, fp16 tiles) + fused logit epilogue, 3 CTAs/SM
// ---------------------------------------------------------------------------
__global__ void __launch_bounds__(256, 3)
k_tedge(const float* __restrict__ ea, const float* __restrict__ Wc,
        const int* __restrict__ ei,
        const float* __restrict__ b1, const float* __restrict__ W2,
        const float* __restrict__ b2, int n_edges) {
    extern __shared__ char smraw[];
    float* b1s = reinterpret_cast<float*>(smraw);
    float* w2s = b1s + 128;
    __half* Ah = reinterpret_cast<__half*>(smraw + OFF_AH);
    __half* Bh = reinterpret_cast<__half*>(smraw + OFF_BH);
    float*  Cs = reinterpret_cast<float*>(smraw + OFF_BH);   // reuse B post-MMA
    int tid = threadIdx.x, wid = tid >> 5;
    int m_base = blockIdx.x * 64;
    int wm = (wid >> 2) * 32, wn = (wid & 3) * 32;

    if (tid < 128) { b1s[tid] = b1[tid]; w2s[tid] = W2[tid]; }
    load_A16(ea, m_base, n_edges, Ah, tid);
    load_B16(Wc, Bh, tid);
    __syncthreads();

    CFrag acc[2][2];
    mma_loop16(Ah, Bh, wm, wn, acc);
    __syncthreads();                 // all warps done reading Bh before C reuse

    #pragma unroll
    for (int i = 0; i < 2; ++i)
        #pragma unroll
        for (int j = 0; j < 2; ++j)
            wmma::store_matrix_sync(Cs + (wm + i * 16) * LDC + wn + j * 16,
                                    acc[i][j], LDC, wmma::mem_row_major);
    __syncthreads();

    // Epilogue: 4 threads per edge row, each owns 32 cols (8 float4)
    int er = tid >> 2;
    int part = tid & 3;
    int e = m_base + er;
    float s = 0.f;
    if (e < n_edges) {
        int r = ei[e];
        int c = ei[n_edges + e];
        int qo = part * 8;
        const float4* cp4 = reinterpret_cast<const float4*>(Cs + er * LDC) + qo;
        const float4* up  = reinterpret_cast<const float4*>(g_u + (size_t)r * HID) + qo;
        const float4* vp  = reinterpret_cast<const float4*>(g_v + (size_t)c * HID) + qo;
        const float4* bb4 = reinterpret_cast<const float4*>(b1s) + qo;
        const float4* ww4 = reinterpret_cast<const float4*>(w2s) + qo;
        #pragma unroll
        for (int q = 0; q < 8; ++q) {
            float4 cv = cp4[q], uu = up[q], vv = vp[q], bb = bb4[q], ww = ww4[q];
            float p0 = cv.x + uu.x + vv.x + bb.x;
            float p1 = cv.y + uu.y + vv.y + bb.y;
            float p2 = cv.z + uu.z + vv.z + bb.z;
            float p3 = cv.w + uu.w + vv.w + bb.w;
            float e0 = p0 > 0.f ? p0 : expm1f(p0);
            float e1 = p1 > 0.f ? p1 : expm1f(p1);
            float e2 = p2 > 0.f ? p2 : expm1f(p2);
            float e3 = p3 > 0.f ? p3 : expm1f(p3);
            s = fmaf(e0, ww.x, s);
            s = fmaf(e1, ww.y, s);
            s = fmaf(e2, ww.z, s);
            s = fmaf(e3, ww.w, s);
        }
    }
    s += __shfl_xor_sync(0xffffffffu, s, 1);
    s += __shfl_xor_sync(0xffffffffu, s, 2);
    if (part == 0 && e < n_edges) {
        float av = s + b2[0];
        av = av >= 0.f ? av : 0.2f * av;
        g_a[e] = av;
    }
}

// ---------------------------------------------------------------------------
// K3/K4: global softmax reduction
// ---------------------------------------------------------------------------
__global__ void k_sm1(int n) {
    __shared__ float sh[256];
    int tid = threadIdx.x;
    float m = -1e30f;
    for (int i = blockIdx.x * 256 + tid; i < n; i += gridDim.x * 256)
        m = fmaxf(m, g_a[i]);
    sh[tid] = m; __syncthreads();
    for (int off = 128; off > 0; off >>= 1) {
        if (tid < off) sh[tid] = fmaxf(sh[tid], sh[tid + off]);
        __syncthreads();
    }
    float bm = sh[0]; __syncthreads();
    float s = 0.f;
    for (int i = blockIdx.x * 256 + tid; i < n; i += gridDim.x * 256)
        s += expf(g_a[i] - bm);
    sh[tid] = s; __syncthreads();
    for (int off = 128; off > 0; off >>= 1) {
        if (tid < off) sh[tid] += sh[tid + off];
        __syncthreads();
    }
    if (tid == 0) { g_pm[blockIdx.x] = bm; g_ps[blockIdx.x] = sh[0]; }
}

__global__ void k_sm2() {
    __shared__ float sh[SM1_BLOCKS];
    int tid = threadIdx.x;
    sh[tid] = g_pm[tid]; __syncthreads();
    for (int off = SM1_BLOCKS / 2; off > 0; off >>= 1) {
        if (tid < off) sh[tid] = fmaxf(sh[tid], sh[tid + off]);
        __syncthreads();
    }
    float M = sh[0]; __syncthreads();
    sh[tid] = g_ps[tid] * expf(g_pm[tid] - M); __syncthreads();
    for (int off = SM1_BLOCKS / 2; off > 0; off >>= 1) {
        if (tid < off) sh[tid] += sh[tid + off];
        __syncthreads();
    }
    if (tid == 0) { g_M = M; g_S = sh[0]; }
}

// ---------------------------------------------------------------------------
// K5/K6: zero + scatter (vector red.global.add.v4.f32)
// ---------------------------------------------------------------------------
__global__ void k_zero(float* __restrict__ out, int n) {
    for (int i = blockIdx.x * blockDim.x + threadIdx.x; i < n;
         i += gridDim.x * blockDim.x)
        out[i] = 0.f;
}

__global__ void k_scatter(const int* __restrict__ ei,
                          const float* __restrict__ h,
                          float* __restrict__ out, int n_edges) {
    int gw = (blockIdx.x * blockDim.x + threadIdx.x) >> 5;
    int lane = threadIdx.x & 31;
    int nw = (gridDim.x * blockDim.x) >> 5;
    float M = g_M;
    float invS = 1.0f / g_S;
    for (int e = gw; e < n_edges; e += nw) {
        int r = ei[e];
        int c = ei[n_edges + e];
        float alpha = expf(g_a[e] - M) * invS;
        float4 hv = reinterpret_cast<const float4*>(h + (size_t)c * HID)[lane];
        float* op = out + (size_t)r * HID + lane * 4;
        asm volatile("red.global.add.v4.f32 [%0], {%1, %2, %3, %4};"
                     :: "l"(op), "f"(alpha * hv.x), "f"(alpha * hv.y),
                        "f"(alpha * hv.z), "f"(alpha * hv.w) : "memory");
    }
}

// ---------------------------------------------------------------------------
extern "C" void kernel_launch(void* const* d_in, const int* in_sizes, int n_in,
                              void* d_out, int out_size) {
    const float* h  = (const float*)d_in[0];
    const int*   ei = (const int*)d_in[1];
    const float* ea = (const float*)d_in[2];
    const float* W1 = (const float*)d_in[3];
    const float* b1 = (const float*)d_in[4];
    const float* W2 = (const float*)d_in[5];
    const float* b2 = (const float*)d_in[6];
    float* out = (float*)d_out;

    int n_nodes = in_sizes[0] / HID;
    int n_edges = in_sizes[2] / HID;

    cudaFuncSetAttribute(k_tguv,  cudaFuncAttributeMaxDynamicSharedMemorySize, SMEM_TILE);
    cudaFuncSetAttribute(k_tedge, cudaFuncAttributeMaxDynamicSharedMemorySize, SMEM_TILE);

    int node_blocks = (n_nodes + 63) / 64;
    int edge_blocks = (n_edges + 63) / 64;

    k_zero<<<2048, 256>>>(out, n_nodes * HID);
    k_tguv<<<node_blocks, 256, SMEM_TILE>>>(h, W1, n_nodes);
    k_tedge<<<edge_blocks, 256, SMEM_TILE>>>(ea, W1 + 2 * HID * HID, ei, b1, W2, b2, n_edges);
    k_sm1<<<SM1_BLOCKS, 256>>>(n_edges);
    k_sm2<<<1, SM1_BLOCKS>>>();
    k_scatter<<<4096, 256>>>(ei, h, out, n_edges);
}